// round 13
// baseline (speedup 1.0000x reference)
#include <cuda_runtime.h>

#define N_SYM 128
#define LEVERAGE 30.0f
#define PF 6   // prefetch depth (iterations of load buffers in flight)

__device__ __forceinline__ float step1(float f, float e, float p, float m,
                                       float um, float st, float rst,
                                       float mn, float mx, float& um_out)
{
    float tm  = m * LEVERAGE;
    float us  = um * tm;
    float mps = fabsf(p) + us;
    float adj = fminf((p * f > 0.0f) ? us : mps, 0.0f);
    float nps = f * (mps - adj);
    float an  = fabsf(nps);
    an = floorf(an * rst) * st;
    an = (an < mn) ? 0.0f : an;
    an = fminf(an, mx);
    um_out = __fdividef(mps - an, tm);
    return (e > 0.5f) ? copysignf(an, nps) : p;
}

__global__ void __launch_bounds__(256)
lowlevel_scan_kernel(
    const float2* __restrict__ F,   // [N_SYM, B2]
    const float2* __restrict__ E,
    const float2* __restrict__ P,
    const float2* __restrict__ M,
    const float2* __restrict__ UM,  // [B2]
    const float*  __restrict__ msm_min,
    const float*  __restrict__ msm_step,
    const float*  __restrict__ msm_max,
    float2* __restrict__ out_nps,   // [N_SYM, B2]
    float2* __restrict__ out_um,    // [B2] or nullptr
    int B2)
{
    __shared__ float s_mn[N_SYM];
    __shared__ float s_st[N_SYM];
    __shared__ float s_rst[N_SYM];
    __shared__ float s_mx[N_SYM];

    int t = threadIdx.x;
    if (t < N_SYM) {
        float st = msm_step[t];
        s_st[t]  = st;
        s_rst[t] = 1.0f / st;
        s_mn[t]  = msm_min[t];
        s_mx[t]  = msm_max[t];
    }
    __syncthreads();

    int c = blockIdx.x * blockDim.x + t;
    if (c >= B2) return;

    float2 um = UM[c];

    // Rotating register buffers: PF iterations of loads in flight.
    // Reads evict-first: lines are dead immediately after consumption.
    float2 bf[PF], be[PF], bp[PF], bm[PF];
#pragma unroll
    for (int i = 0; i < PF; ++i) {
        int id = i * B2 + c;
        bf[i] = __ldcs(&F[id]); be[i] = __ldcs(&E[id]);
        bp[i] = __ldcs(&P[id]); bm[i] = __ldcs(&M[id]);
    }

    // PF=6 is not a power of two: track slot index explicitly.
    int j = 0;
#pragma unroll 6
    for (int s = 0; s < N_SYM; ++s) {
        float2 f = bf[j], e = be[j], p = bp[j], m = bm[j];

        // refill buffer slot j with iteration s+PF (issued early, overlaps compute)
        if (s + PF < N_SYM) {
            int id = (s + PF) * B2 + c;
            bf[j] = __ldcs(&F[id]); be[j] = __ldcs(&E[id]);
            bp[j] = __ldcs(&P[id]); bm[j] = __ldcs(&M[id]);
        }
        j = (j + 1 == PF) ? 0 : j + 1;

        float st = s_st[s], rst = s_rst[s], mn = s_mn[s], mx = s_mx[s];

        float2 o;
        o.x = step1(f.x, e.x, p.x, m.x, um.x, st, rst, mn, mx, um.x);
        o.y = step1(f.y, e.y, p.y, m.y, um.y, st, rst, mn, mx, um.y);
        __stwt(&out_nps[s * B2 + c], o);   // write-through: no L2 dirty-line residency
    }

    if (out_um != nullptr) __stwt(&out_um[c], um);
}

extern "C" void kernel_launch(void* const* d_in, const int* in_sizes, int n_in,
                              void* d_out, int out_size)
{
    const float* fractions     = (const float*)d_in[0];
    const float* exec_samples  = (const float*)d_in[1];
    const float* pos_sizes     = (const float*)d_in[2];
    const float* margin_rates  = (const float*)d_in[3];
    const float* unused_margin = (const float*)d_in[4];
    const float* msm_min       = (const float*)d_in[5];
    const float* msm_step      = (const float*)d_in[6];
    const float* msm_max       = (const float*)d_in[7];

    int B  = in_sizes[4];     // BATCH
    int B2 = B / 2;           // float2 columns

    float* out_nps = (float*)d_out;
    float* out_um  = nullptr;
    if ((long long)out_size >= (long long)N_SYM * B + B)
        out_um = out_nps + (size_t)N_SYM * B;

    int threads = 256;
    int blocks  = (B2 + threads - 1) / threads;   // 256 CTAs for B=131072
    lowlevel_scan_kernel<<<blocks, threads>>>(
        (const float2*)fractions, (const float2*)exec_samples,
        (const float2*)pos_sizes, (const float2*)margin_rates,
        (const float2*)unused_margin,
        msm_min, msm_step, msm_max,
        (float2*)out_nps, (float2*)out_um, B2);
}

// round 14
// speedup vs baseline: 1.1101x; 1.1101x over previous
#include <cuda_runtime.h>

#define N_SYM 128
#define LEVERAGE 30.0f
#define PF 4   // prefetch depth (iterations of load buffers in flight)

__device__ __forceinline__ float step1(float f, float e, float p, float m,
                                       float um, float st, float rst,
                                       float mn, float mx, float& um_out)
{
    float tm  = m * LEVERAGE;
    float us  = um * tm;
    float mps = fabsf(p) + us;
    float adj = fminf((p * f > 0.0f) ? us : mps, 0.0f);
    float nps = f * (mps - adj);
    float an  = fabsf(nps);
    an = floorf(an * rst) * st;
    an = (an < mn) ? 0.0f : an;
    an = fminf(an, mx);
    um_out = __fdividef(mps - an, tm);
    return (e > 0.5f) ? copysignf(an, nps) : p;
}

__global__ void __launch_bounds__(256)
lowlevel_scan_kernel(
    const float2* __restrict__ F,   // [N_SYM, B2]
    const float2* __restrict__ E,
    const float2* __restrict__ P,
    const float2* __restrict__ M,
    const float2* __restrict__ UM,  // [B2]
    const float*  __restrict__ msm_min,
    const float*  __restrict__ msm_step,
    const float*  __restrict__ msm_max,
    float2* __restrict__ out_nps,   // [N_SYM, B2]
    float2* __restrict__ out_um,    // [B2] or nullptr
    int B2)
{
    __shared__ float s_mn[N_SYM];
    __shared__ float s_st[N_SYM];
    __shared__ float s_rst[N_SYM];
    __shared__ float s_mx[N_SYM];

    int t = threadIdx.x;
    if (t < N_SYM) {
        float st = msm_step[t];
        s_st[t]  = st;
        s_rst[t] = 1.0f / st;
        s_mn[t]  = msm_min[t];
        s_mx[t]  = msm_max[t];
    }
    __syncthreads();

    int c = blockIdx.x * blockDim.x + t;
    if (c >= B2) return;

    float2 um = UM[c];

    // Rotating register buffers: PF iterations of loads in flight.
    // Reads evict-first: lines are dead immediately after consumption.
    float2 bf[PF], be[PF], bp[PF], bm[PF];
#pragma unroll
    for (int i = 0; i < PF; ++i) {
        int id = i * B2 + c;
        bf[i] = __ldcs(&F[id]); be[i] = __ldcs(&E[id]);
        bp[i] = __ldcs(&P[id]); bm[i] = __ldcs(&M[id]);
    }

#pragma unroll 4
    for (int s = 0; s < N_SYM; ++s) {
        int j = s & (PF - 1);
        float2 f = bf[j], e = be[j], p = bp[j], m = bm[j];

        // refill buffer slot j with iteration s+PF (issued early, overlaps compute)
        if (s + PF < N_SYM) {
            int id = (s + PF) * B2 + c;
            bf[j] = __ldcs(&F[id]); be[j] = __ldcs(&E[id]);
            bp[j] = __ldcs(&P[id]); bm[j] = __ldcs(&M[id]);
        }

        float st = s_st[s], rst = s_rst[s], mn = s_mn[s], mx = s_mx[s];

        float2 o;
        o.x = step1(f.x, e.x, p.x, m.x, um.x, st, rst, mn, mx, um.x);
        o.y = step1(f.y, e.y, p.y, m.y, um.y, st, rst, mn, mx, um.y);
        __stwt(&out_nps[s * B2 + c], o);   // write-through: no L2 dirty-line residency
    }

    if (out_um != nullptr) __stwt(&out_um[c], um);
}

extern "C" void kernel_launch(void* const* d_in, const int* in_sizes, int n_in,
                              void* d_out, int out_size)
{
    const float* fractions     = (const float*)d_in[0];
    const float* exec_samples  = (const float*)d_in[1];
    const float* pos_sizes     = (const float*)d_in[2];
    const float* margin_rates  = (const float*)d_in[3];
    const float* unused_margin = (const float*)d_in[4];
    const float* msm_min       = (const float*)d_in[5];
    const float* msm_step      = (const float*)d_in[6];
    const float* msm_max       = (const float*)d_in[7];

    int B  = in_sizes[4];     // BATCH
    int B2 = B / 2;           // float2 columns

    float* out_nps = (float*)d_out;
    float* out_um  = nullptr;
    if ((long long)out_size >= (long long)N_SYM * B + B)
        out_um = out_nps + (size_t)N_SYM * B;

    int threads = 256;
    int blocks  = (B2 + threads - 1) / threads;   // 256 CTAs for B=131072
    lowlevel_scan_kernel<<<blocks, threads>>>(
        (const float2*)fractions, (const float2*)exec_samples,
        (const float2*)pos_sizes, (const float2*)margin_rates,
        (const float2*)unused_margin,
        msm_min, msm_step, msm_max,
        (float2*)out_nps, (float2*)out_um, B2);
}